// round 7
// baseline (speedup 1.0000x reference)
#include <cuda_runtime.h>
#include <cuda_bf16.h>
#include <cstdint>

#define N_NODES 100000
#define N_EDGES 800000
#define SCAN_CHUNK 400

typedef unsigned long long ull;

// ------------------------- device scratch (no allocs) ------------------------
__device__ __align__(16) float g_h[(size_t)N_NODES * 128];   // layer1 output
__device__ int g_cnt[N_NODES];
__device__ int g_off[N_NODES + 1];
__device__ int g_cur[N_NODES];
__device__ int g_esrc[N_EDGES];
__device__ int g_bsum[512];
__device__ int g_bpre[512];

// ------------------------------ f32x2 helpers --------------------------------
__device__ __forceinline__ ull dup2(float f) {
    ull r; unsigned u = __float_as_uint(f);
    asm("mov.b64 %0, {%1, %1};" : "=l"(r) : "r"(u));
    return r;
}
__device__ __forceinline__ float2 unpack2(ull v) {
    unsigned a, b;
    asm("mov.b64 {%0, %1}, %2;" : "=r"(a), "=r"(b) : "l"(v));
    return make_float2(__uint_as_float(a), __uint_as_float(b));
}
__device__ __forceinline__ void ffma2(ull& d, ull a, ull b) {
    asm("fma.rn.f32x2 %0, %1, %2, %0;" : "+l"(d) : "l"(a), "l"(b));
}

// ------------------------------ CSR build ------------------------------------
__global__ void zero_kernel(int* p, int n) {
    int i = blockIdx.x * blockDim.x + threadIdx.x;
    if (i < n) p[i] = 0;
}
__global__ void hist_kernel(const int* __restrict__ dst, int* __restrict__ cnt, int n_edges) {
    int e = blockIdx.x * blockDim.x + threadIdx.x;
    if (e < n_edges) atomicAdd(&cnt[dst[e]], 1);
}
__global__ void scan_part_kernel(const int* __restrict__ cnt, int* __restrict__ bsum, int n) {
    __shared__ int red[256];
    int b = blockIdx.x, t = threadIdx.x;
    int s = 0;
    for (int i = t; i < SCAN_CHUNK; i += 256) {
        int idx = b * SCAN_CHUNK + i;
        if (idx < n) s += cnt[idx];
    }
    red[t] = s;
    __syncthreads();
    for (int d = 128; d > 0; d >>= 1) {
        if (t < d) red[t] += red[t + d];
        __syncthreads();
    }
    if (t == 0) bsum[b] = red[0];
}
__global__ void scan_bsum_kernel(const int* __restrict__ bsum, int* __restrict__ bpre,
                                 int nblocks, int* __restrict__ off, int n, int n_edges) {
    __shared__ int s[512];
    int t = threadIdx.x;
    s[t] = (t < nblocks) ? bsum[t] : 0;
    s[t + 256] = (t + 256 < nblocks) ? bsum[t + 256] : 0;
    __syncthreads();
    for (int d = 1; d < 512; d <<= 1) {
        int v0 = (t >= d) ? s[t - d] : 0;
        int v1 = s[t + 256 - d];
        __syncthreads();
        s[t] += v0;
        s[t + 256] += v1;
        __syncthreads();
    }
    if (t < nblocks) bpre[t] = s[t] - bsum[t];
    if (t + 256 < nblocks) bpre[t + 256] = s[t + 256] - bsum[t + 256];
    if (t == 0) off[n] = n_edges;
}
__global__ void scan_emit_kernel(const int* __restrict__ cnt, const int* __restrict__ bpre,
                                 int* __restrict__ off, int* __restrict__ cur, int n) {
    __shared__ int s[512];
    int b = blockIdx.x, t = threadIdx.x;
    #pragma unroll
    for (int h = 0; h < 2; h++) {
        int i = t + h * 256;
        int idx = b * SCAN_CHUNK + i;
        s[i] = (i < SCAN_CHUNK && idx < n) ? cnt[idx] : 0;
    }
    __syncthreads();
    for (int d = 1; d < 512; d <<= 1) {
        int v0 = (t >= d) ? s[t - d] : 0;
        int v1 = s[t + 256 - d];
        __syncthreads();
        s[t] += v0;
        s[t + 256] += v1;
        __syncthreads();
    }
    int base = bpre[b];
    #pragma unroll
    for (int h = 0; h < 2; h++) {
        int i = t + h * 256;
        int idx = b * SCAN_CHUNK + i;
        if (i < SCAN_CHUNK && idx < n) {
            int excl = base + (i ? s[i - 1] : 0);
            off[idx] = excl;
            cur[idx] = excl;
        }
    }
}
__global__ void fill_kernel(const int* __restrict__ src, const int* __restrict__ dst,
                            int* __restrict__ cur, int* __restrict__ esrc, int n_edges) {
    int e = blockIdx.x * blockDim.x + threadIdx.x;
    if (e >= n_edges) return;
    int d = dst[e];
    int p = atomicAdd(&cur[d], 1);
    esrc[p] = src[e];
}

// ---------------- gather one tile into k-major smem buffer -------------------
// worker granularity: D/4 lanes handle one node's row (16 lanes for D=64,
// full warp for D=128). Writes zTb[k][node_local], zero-padded tail.
template <int D, int TILE, int PAD>
__device__ __forceinline__ void gather_tile(
    const float* __restrict__ feat, const int* __restrict__ off,
    const int* __restrict__ esrc, float sc, float* zTb,
    int tile0, int n_nodes, int worker, int nworkers, int l) {
    for (int nl = worker; nl < TILE; nl += nworkers) {
        int node = tile0 + nl;
        float4 r = make_float4(0.f, 0.f, 0.f, 0.f);
        if (node < n_nodes) {
            float4 self = reinterpret_cast<const float4*>(feat + (size_t)node * D)[l];
            float4 acc = make_float4(0.f, 0.f, 0.f, 0.f);
            int e0 = __ldg(&off[node]), e1 = __ldg(&off[node + 1]);
            for (int e = e0; e < e1; e++) {
                int s = __ldg(&esrc[e]);
                float4 v = reinterpret_cast<const float4*>(feat + (size_t)s * D)[l];
                acc.x += v.x; acc.y += v.y; acc.z += v.z; acc.w += v.w;
            }
            r = make_float4(fmaf(sc, self.x, acc.x), fmaf(sc, self.y, acc.y),
                            fmaf(sc, self.z, acc.z), fmaf(sc, self.w, acc.w));
        }
        zTb[(4 * l + 0) * PAD + nl] = r.x;
        zTb[(4 * l + 1) * PAD + nl] = r.y;
        zTb[(4 * l + 2) * PAD + nl] = r.z;
        zTb[(4 * l + 3) * PAD + nl] = r.w;
    }
}

// ---------------- MLP over one tile (256 threads, warps 0-7) -----------------
template <int D_IN, int D_OUT, int TILE, int PAD, bool RELU_OUT>
__device__ __forceinline__ void mlp_tile(
    const float* zTb, const float* Wa_s, const float* Wb_s,
    const float* ba_s, const float* bb_s, float* hT,
    float* __restrict__ out, int tile0, int n_nodes, int tid) {
    constexpr int DH = 128;
    constexpr int NPG1 = TILE / 8;
    constexpr int NP1 = NPG1 / 2;
    constexpr int CG = D_OUT / 4;
    constexpr int NG2 = 256 / CG;
    constexpr int NPG2 = TILE / NG2;
    constexpr int NP2 = NPG2 / 2;

    // ---- stage 1: hidden = relu(z @ Wa + ba) ----
    {
        const int tx = tid & 31;
        const int ty = tid >> 5;
        const float* zrow0 = zTb + ty * NPG1;
        ull acc[NP1][4];
        {
            float4 b = *reinterpret_cast<const float4*>(ba_s + 4 * tx);
            ull b0 = dup2(b.x), b1 = dup2(b.y), b2 = dup2(b.z), b3 = dup2(b.w);
            #pragma unroll
            for (int p = 0; p < NP1; p++) { acc[p][0] = b0; acc[p][1] = b1; acc[p][2] = b2; acc[p][3] = b3; }
        }
        #pragma unroll 4
        for (int k = 0; k < D_IN; k++) {
            ull zp[NP1];
            #pragma unroll
            for (int p = 0; p < NP1; p++)
                zp[p] = *reinterpret_cast<const ull*>(zrow0 + k * PAD + 2 * p);
            float4 w = *reinterpret_cast<const float4*>(Wa_s + k * DH + 4 * tx);
            ull w0 = dup2(w.x), w1 = dup2(w.y), w2 = dup2(w.z), w3 = dup2(w.w);
            #pragma unroll
            for (int p = 0; p < NP1; p++) {
                ffma2(acc[p][0], zp[p], w0);
                ffma2(acc[p][1], zp[p], w1);
                ffma2(acc[p][2], zp[p], w2);
                ffma2(acc[p][3], zp[p], w3);
            }
        }
        #pragma unroll
        for (int p = 0; p < NP1; p++) {
            #pragma unroll
            for (int c = 0; c < 4; c++) {
                float2 v = unpack2(acc[p][c]);
                v.x = fmaxf(v.x, 0.f);
                v.y = fmaxf(v.y, 0.f);
                *reinterpret_cast<float2*>(hT + (4 * tx + c) * PAD + ty * NPG1 + 2 * p) = v;
            }
        }
    }
    asm volatile("bar.sync 1, 256;" ::: "memory");

    // ---- stage 2: out = [relu](hidden @ Wb + bb) ----
    {
        const int tx = tid % CG;
        const int ty = tid / CG;
        const float* hrow0 = hT + ty * NPG2;
        ull acc[NP2][4];
        {
            float4 b = *reinterpret_cast<const float4*>(bb_s + 4 * tx);
            ull b0 = dup2(b.x), b1 = dup2(b.y), b2 = dup2(b.z), b3 = dup2(b.w);
            #pragma unroll
            for (int p = 0; p < NP2; p++) { acc[p][0] = b0; acc[p][1] = b1; acc[p][2] = b2; acc[p][3] = b3; }
        }
        #pragma unroll 4
        for (int k = 0; k < DH; k++) {
            ull zp[NP2];
            #pragma unroll
            for (int p = 0; p < NP2; p++)
                zp[p] = *reinterpret_cast<const ull*>(hrow0 + k * PAD + 2 * p);
            float4 w = *reinterpret_cast<const float4*>(Wb_s + k * D_OUT + 4 * tx);
            ull w0 = dup2(w.x), w1 = dup2(w.y), w2 = dup2(w.z), w3 = dup2(w.w);
            #pragma unroll
            for (int p = 0; p < NP2; p++) {
                ffma2(acc[p][0], zp[p], w0);
                ffma2(acc[p][1], zp[p], w1);
                ffma2(acc[p][2], zp[p], w2);
                ffma2(acc[p][3], zp[p], w3);
            }
        }
        #pragma unroll
        for (int p = 0; p < NP2; p++) {
            float2 c0 = unpack2(acc[p][0]);
            float2 c1 = unpack2(acc[p][1]);
            float2 c2 = unpack2(acc[p][2]);
            float2 c3 = unpack2(acc[p][3]);
            #pragma unroll
            for (int half = 0; half < 2; half++) {
                int node = tile0 + ty * NPG2 + 2 * p + half;
                if (node >= n_nodes) continue;
                float4 v = half ? make_float4(c0.y, c1.y, c2.y, c3.y)
                                : make_float4(c0.x, c1.x, c2.x, c3.x);
                if (RELU_OUT) {
                    v.x = fmaxf(v.x, 0.f); v.y = fmaxf(v.y, 0.f);
                    v.z = fmaxf(v.z, 0.f); v.w = fmaxf(v.w, 0.f);
                }
                reinterpret_cast<float4*>(out + (size_t)node * D_OUT)[tx] = v;
            }
        }
    }
}

// -------- persistent fused layer: gather (warps 8-11) || MLP (warps 0-7) -----
template <int D_IN, int D_OUT, int TILE, bool RELU_OUT>
__global__ void __launch_bounds__(384, 1)
gin_layer_kernel(const float* __restrict__ feat, const int* __restrict__ off,
                 const int* __restrict__ esrc, const float* __restrict__ epsp,
                 const float* __restrict__ Wa, const float* __restrict__ ba,
                 const float* __restrict__ Wb, const float* __restrict__ bb,
                 float* __restrict__ out, int n_nodes, int ntiles) {
    constexpr int DH = 128;
    constexpr int PAD = TILE + 4;
    constexpr int LPW = D_IN / 4;   // lanes per gather worker
    extern __shared__ float sm[];
    float* Wa_s = sm;                          // D_IN * DH
    float* Wb_s = Wa_s + D_IN * DH;            // DH * D_OUT
    float* ba_s = Wb_s + DH * D_OUT;           // 128
    float* bb_s = ba_s + 128;                  // 128
    float* zT0  = bb_s + 128;                  // D_IN * PAD
    float* zT1  = zT0 + D_IN * PAD;            // D_IN * PAD
    float* hT   = zT1 + D_IN * PAD;            // DH * PAD

    const int tid = threadIdx.x;
    for (int i = tid; i < D_IN * DH; i += 384) Wa_s[i] = Wa[i];
    for (int i = tid; i < DH * D_OUT; i += 384) Wb_s[i] = Wb[i];
    if (tid < DH) ba_s[tid] = ba[tid];
    if (tid < D_OUT) bb_s[tid] = bb[tid];
    const float sc = 1.0f + *epsp;

    // prologue: all 384 threads gather the first tile into zT0
    {
        int w0 = tid / LPW, nw0 = 384 / LPW, l = tid % LPW;
        gather_tile<D_IN, TILE, PAD>(feat, off, esrc, sc, zT0,
                                     blockIdx.x * TILE, n_nodes, w0, nw0, l);
    }
    __syncthreads();

    int cur = 0;
    for (int t = blockIdx.x; t < ntiles; t += gridDim.x) {
        float* zc = cur ? zT1 : zT0;
        float* zn = cur ? zT0 : zT1;
        if (tid < 256) {
            mlp_tile<D_IN, D_OUT, TILE, PAD, RELU_OUT>(
                zc, Wa_s, Wb_s, ba_s, bb_s, hT, out, t * TILE, n_nodes, tid);
        } else {
            int tn = t + gridDim.x;
            if (tn < ntiles) {
                int w = (tid - 256) / LPW, nw = 128 / LPW, l = tid % LPW;
                gather_tile<D_IN, TILE, PAD>(feat, off, esrc, sc, zn,
                                             tn * TILE, n_nodes, w, nw, l);
            }
        }
        __syncthreads();
        cur ^= 1;
    }
}

// ---------------------------------- launch -----------------------------------
extern "C" void kernel_launch(void* const* d_in, const int* in_sizes, int n_in,
                              void* d_out, int out_size) {
    const float* x    = (const float*)d_in[0];
    const int*   ei   = (const int*)d_in[1];
    const float* eps1 = (const float*)d_in[2];
    const float* eps2 = (const float*)d_in[3];
    const float* W1a  = (const float*)d_in[4];
    const float* b1a  = (const float*)d_in[5];
    const float* W1b  = (const float*)d_in[6];
    const float* b1b  = (const float*)d_in[7];
    const float* W2a  = (const float*)d_in[8];
    const float* b2a  = (const float*)d_in[9];
    const float* W2b  = (const float*)d_in[10];
    const float* b2b  = (const float*)d_in[11];
    float* out = (float*)d_out;

    const int n_nodes = in_sizes[0] / 64;
    const int n_edges = in_sizes[1] / 2;
    const int* src = ei;
    const int* dst = ei + n_edges;

    float* h;
    int *cnt, *off, *cur, *esrc, *bsum, *bpre;
    cudaGetSymbolAddress((void**)&h,  g_h);
    cudaGetSymbolAddress((void**)&cnt, g_cnt);
    cudaGetSymbolAddress((void**)&off, g_off);
    cudaGetSymbolAddress((void**)&cur, g_cur);
    cudaGetSymbolAddress((void**)&esrc, g_esrc);
    cudaGetSymbolAddress((void**)&bsum, g_bsum);
    cudaGetSymbolAddress((void**)&bpre, g_bpre);

    // smem: weights + biases + 2x zT + hT
    // L1: TILE=96, PAD=100 -> (8192+16384+256 + 2*6400 + 12800)*4 = 201,728 B
    // L2: TILE=64, PAD=68  -> (16384+8192+256 + 2*8704 + 8704)*4 = 203,776 B
    const int smem1 = (64 * 128 + 128 * 128 + 256 + 2 * 64 * 100 + 128 * 100) * 4;
    const int smem2 = (128 * 128 + 128 * 64 + 256 + 2 * 128 * 68 + 128 * 68) * 4;
    cudaFuncSetAttribute(gin_layer_kernel<64, 128, 96, true>,
                         cudaFuncAttributeMaxDynamicSharedMemorySize, smem1);
    cudaFuncSetAttribute(gin_layer_kernel<128, 64, 64, false>,
                         cudaFuncAttributeMaxDynamicSharedMemorySize, smem2);

    // ---- CSR build ----
    const int nscan = (n_nodes + SCAN_CHUNK - 1) / SCAN_CHUNK;
    zero_kernel<<<(n_nodes + 255) / 256, 256>>>(cnt, n_nodes);
    hist_kernel<<<(n_edges + 255) / 256, 256>>>(dst, cnt, n_edges);
    scan_part_kernel<<<nscan, 256>>>(cnt, bsum, n_nodes);
    scan_bsum_kernel<<<1, 256>>>(bsum, bpre, nscan, off, n_nodes, n_edges);
    scan_emit_kernel<<<nscan, 256>>>(cnt, bpre, off, cur, n_nodes);
    fill_kernel<<<(n_edges + 255) / 256, 256>>>(src, dst, cur, esrc, n_edges);

    const int GRID = 148;

    // ---- layer 1 (x -> h) ----
    {
        int ntiles = (n_nodes + 95) / 96;
        gin_layer_kernel<64, 128, 96, true><<<GRID, 384, smem1>>>(
            x, off, esrc, eps1, W1a, b1a, W1b, b1b, h, n_nodes, ntiles);
    }
    // ---- layer 2 (h -> out) ----
    {
        int ntiles = (n_nodes + 63) / 64;
        gin_layer_kernel<128, 64, 64, false><<<GRID, 384, smem2>>>(
            h, off, esrc, eps2, W2a, b2a, W2b, b2b, out, n_nodes, ntiles);
    }
}

// round 8
// speedup vs baseline: 1.7598x; 1.7598x over previous
#include <cuda_runtime.h>
#include <cuda_bf16.h>
#include <cstdint>

#define N_NODES 100000
#define N_EDGES 800000
#define SCAN_CHUNK 400

// ------------------------- device scratch (no allocs) ------------------------
__device__ __align__(16) float g_z1[(size_t)N_NODES * 64];
__device__ __align__(16) float g_h [(size_t)N_NODES * 128];
__device__ __align__(16) float g_z2[(size_t)N_NODES * 128];
__device__ int g_cnt[N_NODES];          // zero-initialized at load; re-zeroed at end of each call
__device__ int g_off[N_NODES + 1];
__device__ int g_cur[N_NODES];
__device__ int g_esrc[N_EDGES];
__device__ int g_bsum[512];

// ------------------------------ bf16 helpers ---------------------------------
// pack two bf16 (lower 16 bits = first/lower-k element)
__device__ __forceinline__ unsigned pk(float x, float y) {
    unsigned short a = __bfloat16_as_ushort(__float2bfloat16_rn(x));
    unsigned short b = __bfloat16_as_ushort(__float2bfloat16_rn(y));
    return (unsigned)a | ((unsigned)b << 16);
}
// split pair into hi/lo bf16x2 words
__device__ __forceinline__ void split2(float x, float y, unsigned& hi, unsigned& lo) {
    float xh = __bfloat162float(__float2bfloat16_rn(x));
    float yh = __bfloat162float(__float2bfloat16_rn(y));
    hi = pk(x, y);
    lo = pk(x - xh, y - yh);
}

// m16n8k16 bf16 MMA, fp32 accumulate (row.col)
__device__ __forceinline__ void mma_bf16(float* c, const unsigned* a, const unsigned* b) {
    asm volatile(
        "mma.sync.aligned.m16n8k16.row.col.f32.bf16.bf16.f32 "
        "{%0,%1,%2,%3}, {%4,%5,%6,%7}, {%8,%9}, {%0,%1,%2,%3};"
        : "+f"(c[0]), "+f"(c[1]), "+f"(c[2]), "+f"(c[3])
        : "r"(a[0]), "r"(a[1]), "r"(a[2]), "r"(a[3]), "r"(b[0]), "r"(b[1]));
}

// ------------------------------ CSR build ------------------------------------
__global__ void hist_kernel(const int* __restrict__ dst, int* __restrict__ cnt, int n_edges) {
    int e = blockIdx.x * blockDim.x + threadIdx.x;
    if (e < n_edges) atomicAdd(&cnt[dst[e]], 1);
}
__global__ void scan_part_kernel(const int* __restrict__ cnt, int* __restrict__ bsum, int n) {
    __shared__ int red[256];
    int b = blockIdx.x, t = threadIdx.x;
    int s = 0;
    for (int i = t; i < SCAN_CHUNK; i += 256) {
        int idx = b * SCAN_CHUNK + i;
        if (idx < n) s += cnt[idx];
    }
    red[t] = s;
    __syncthreads();
    for (int d = 128; d > 0; d >>= 1) {
        if (t < d) red[t] += red[t + d];
        __syncthreads();
    }
    if (t == 0) bsum[b] = red[0];
}
// local scan + inline cross-block base (sum of bsum[0..b))
__global__ void scan_emit_kernel(const int* __restrict__ cnt, const int* __restrict__ bsum,
                                 int* __restrict__ off, int* __restrict__ cur,
                                 int n, int n_edges) {
    __shared__ int s[512];
    __shared__ int red[256];
    int b = blockIdx.x, t = threadIdx.x;
    int acc = 0;
    for (int i = t; i < b; i += 256) acc += bsum[i];
    red[t] = acc;
    __syncthreads();
    for (int d = 128; d > 0; d >>= 1) {
        if (t < d) red[t] += red[t + d];
        __syncthreads();
    }
    int base = red[0];
    #pragma unroll
    for (int h = 0; h < 2; h++) {
        int i = t + h * 256;
        int idx = b * SCAN_CHUNK + i;
        s[i] = (i < SCAN_CHUNK && idx < n) ? cnt[idx] : 0;
    }
    __syncthreads();
    for (int d = 1; d < 512; d <<= 1) {
        int v0 = (t >= d) ? s[t - d] : 0;
        int v1 = s[t + 256 - d];
        __syncthreads();
        s[t] += v0;
        s[t + 256] += v1;
        __syncthreads();
    }
    #pragma unroll
    for (int h = 0; h < 2; h++) {
        int i = t + h * 256;
        int idx = b * SCAN_CHUNK + i;
        if (i < SCAN_CHUNK && idx < n) {
            int excl = base + (i ? s[i - 1] : 0);
            off[idx] = excl;
            cur[idx] = excl;
        }
    }
    if (b == 0 && t == 0) off[n] = n_edges;
}
__global__ void fill_kernel(const int* __restrict__ src, const int* __restrict__ dst,
                            int* __restrict__ cur, int* __restrict__ esrc, int n_edges) {
    int e = blockIdx.x * blockDim.x + threadIdx.x;
    if (e >= n_edges) return;
    int d = dst[e];
    int p = atomicAdd(&cur[d], 1);
    esrc[p] = src[e];
}
__global__ void zero_kernel(int* p, int n) {
    int i = blockIdx.x * blockDim.x + threadIdx.x;
    if (i < n) p[i] = 0;
}

// --------------------- gather aggregation:  z = (1+eps)x + sum ---------------
__global__ void gather64_kernel(const float* __restrict__ x,
                                const int* __restrict__ off,
                                const int* __restrict__ esrc,
                                const float* __restrict__ eps,
                                float* __restrict__ z, int n_nodes) {
    int gwarp = (blockIdx.x * blockDim.x + threadIdx.x) >> 5;
    int lane = threadIdx.x & 31;
    int node = gwarp * 2 + (lane >> 4);
    int l = lane & 15;
    if (node >= n_nodes) return;
    float4 self = reinterpret_cast<const float4*>(x + (size_t)node * 64)[l];
    float4 acc = make_float4(0.f, 0.f, 0.f, 0.f);
    int e0 = off[node], e1 = off[node + 1];
    for (int e = e0; e < e1; e++) {
        int s = __ldg(&esrc[e]);
        float4 v = reinterpret_cast<const float4*>(x + (size_t)s * 64)[l];
        acc.x += v.x; acc.y += v.y; acc.z += v.z; acc.w += v.w;
    }
    float sc = 1.0f + *eps;
    float4 r = make_float4(fmaf(sc, self.x, acc.x), fmaf(sc, self.y, acc.y),
                           fmaf(sc, self.z, acc.z), fmaf(sc, self.w, acc.w));
    reinterpret_cast<float4*>(z + (size_t)node * 64)[l] = r;
}
__global__ void gather128_kernel(const float* __restrict__ h,
                                 const int* __restrict__ off,
                                 const int* __restrict__ esrc,
                                 const float* __restrict__ eps,
                                 float* __restrict__ z, int n_nodes) {
    int node = (blockIdx.x * blockDim.x + threadIdx.x) >> 5;
    int l = threadIdx.x & 31;
    if (node >= n_nodes) return;
    float4 self = reinterpret_cast<const float4*>(h + (size_t)node * 128)[l];
    float4 acc = make_float4(0.f, 0.f, 0.f, 0.f);
    int e0 = off[node], e1 = off[node + 1];
    for (int e = e0; e < e1; e++) {
        int s = __ldg(&esrc[e]);
        float4 v = reinterpret_cast<const float4*>(h + (size_t)s * 128)[l];
        acc.x += v.x; acc.y += v.y; acc.z += v.z; acc.w += v.w;
    }
    float sc = 1.0f + *eps;
    float4 r = make_float4(fmaf(sc, self.x, acc.x), fmaf(sc, self.y, acc.y),
                           fmaf(sc, self.z, acc.z), fmaf(sc, self.w, acc.w));
    reinterpret_cast<float4*>(z + (size_t)node * 128)[l] = r;
}

// --------------- MMA MLP: bf16 hi/lo 3-pass emulated-fp32 GEMMs --------------
// Persistent grid. One CTA = 256 threads (8 warps), 64-node tiles.
// Warp (mt = wid/2, nh = wid&1): m-tile mt (16 rows), n-half nh.
// stage1: hidden[64,128] = z[64,D_IN] @ Wa[D_IN,128]  (3 bf16 passes)
// stage2: out[64,D_OUT]  = hidden @ Wb[128,D_OUT]     (3 bf16 passes)
// Weights stored transposed (n-major) + split hi/lo in smem, staged once.
template <int D_IN, int D_OUT, bool RELU_OUT>
__global__ void __launch_bounds__(256, 1)
mlp_mma_kernel(const float* __restrict__ z,
               const float* __restrict__ Wa, const float* __restrict__ ba,
               const float* __restrict__ Wb, const float* __restrict__ bb,
               float* __restrict__ out, int n_nodes, int ntiles) {
    constexpr int DH = 128, TILE = 64;
    constexpr int PA1 = D_IN + 8;     // bf16 elems/row for z and WaT (≡8 mod 64 → conflict-free)
    constexpr int PA2 = DH + 8;       // 136
    constexpr int KT1 = D_IN / 16, KT2 = DH / 16;
    constexpr int NT1 = 8;            // (DH/8) n-tiles / 2 halves
    constexpr int NT2 = D_OUT / 16;
    constexpr int SZ_WaT = DH * PA1 * 2;
    constexpr int SZ_WbT = D_OUT * PA2 * 2;
    constexpr int SZ_Z = TILE * PA1 * 2;
    constexpr int SZ_H = TILE * PA2 * 2;
    constexpr int O_WaH = 0, O_WaL = SZ_WaT;
    constexpr int O_WbH = 2 * SZ_WaT, O_WbL = 2 * SZ_WaT + SZ_WbT;
    constexpr int O_ZH = O_WbL + SZ_WbT, O_ZL = O_ZH + SZ_Z;
    constexpr int O_HH = O_ZL + SZ_Z, O_HL = O_HH + SZ_H;
    constexpr int O_BA = O_HL + SZ_H, O_BB = O_BA + DH * 4;

    extern __shared__ char sm[];
    unsigned short* WaH = (unsigned short*)(sm + O_WaH);
    unsigned short* WaL = (unsigned short*)(sm + O_WaL);
    unsigned short* WbH = (unsigned short*)(sm + O_WbH);
    unsigned short* WbL = (unsigned short*)(sm + O_WbL);
    const unsigned* WaH32 = (const unsigned*)WaH;
    const unsigned* WaL32 = (const unsigned*)WaL;
    const unsigned* WbH32 = (const unsigned*)WbH;
    const unsigned* WbL32 = (const unsigned*)WbL;
    unsigned* zH32 = (unsigned*)(sm + O_ZH);
    unsigned* zL32 = (unsigned*)(sm + O_ZL);
    unsigned* hH32 = (unsigned*)(sm + O_HH);
    unsigned* hL32 = (unsigned*)(sm + O_HL);
    float* ba_s = (float*)(sm + O_BA);
    float* bb_s = (float*)(sm + O_BB);

    const int tid = threadIdx.x;
    const int wid = tid >> 5, lane = tid & 31;
    const int g = lane >> 2, q = lane & 3;
    const int mt = wid >> 1, nh = wid & 1;
    const int r0 = mt * 16 + g;

    // ---- stage weights (once per CTA): WaT[n][k], WbT[n][k], split hi/lo ----
    for (int i = tid; i < D_IN * DH; i += 256) {
        int k = i / DH, n = i % DH;
        float v = Wa[i];
        float vh = __bfloat162float(__float2bfloat16_rn(v));
        WaH[n * PA1 + k] = __bfloat16_as_ushort(__float2bfloat16_rn(v));
        WaL[n * PA1 + k] = __bfloat16_as_ushort(__float2bfloat16_rn(v - vh));
    }
    for (int i = tid; i < DH * D_OUT; i += 256) {
        int k = i / D_OUT, n = i % D_OUT;
        float v = Wb[i];
        float vh = __bfloat162float(__float2bfloat16_rn(v));
        WbH[n * PA2 + k] = __bfloat16_as_ushort(__float2bfloat16_rn(v));
        WbL[n * PA2 + k] = __bfloat16_as_ushort(__float2bfloat16_rn(v - vh));
    }
    if (tid < DH) ba_s[tid] = ba[tid];
    if (tid < D_OUT) bb_s[tid] = bb[tid];
    __syncthreads();

    for (int t = blockIdx.x; t < ntiles; t += gridDim.x) {
        const int tile0 = t * TILE;

        // ---- stage z tile: split into zHi/zLo bf16 [row][k] ----
        for (int i = tid; i < TILE * (D_IN / 4); i += 256) {
            int r = i / (D_IN / 4);
            int kc = i % (D_IN / 4);
            int node = tile0 + r;
            float4 v = (node < n_nodes)
                     ? reinterpret_cast<const float4*>(z + (size_t)node * D_IN)[kc]
                     : make_float4(0.f, 0.f, 0.f, 0.f);
            unsigned h0, l0, h1, l1;
            split2(v.x, v.y, h0, l0);
            split2(v.z, v.w, h1, l1);
            int idx = r * (PA1 / 2) + kc * 2;
            *reinterpret_cast<uint2*>(zH32 + idx) = make_uint2(h0, h1);
            *reinterpret_cast<uint2*>(zL32 + idx) = make_uint2(l0, l1);
        }
        __syncthreads();

        // ---- stage 1 ----
        float c1[NT1][4];
        #pragma unroll
        for (int nt = 0; nt < NT1; nt++)
            #pragma unroll
            for (int j = 0; j < 4; j++) c1[nt][j] = 0.f;
        #pragma unroll
        for (int kt = 0; kt < KT1; kt++) {
            unsigned aH[4], aL[4];
            int ia0 = r0 * (PA1 / 2) + kt * 8 + q;
            int ia1 = (r0 + 8) * (PA1 / 2) + kt * 8 + q;
            aH[0] = zH32[ia0]; aH[1] = zH32[ia1]; aH[2] = zH32[ia0 + 4]; aH[3] = zH32[ia1 + 4];
            aL[0] = zL32[ia0]; aL[1] = zL32[ia1]; aL[2] = zL32[ia0 + 4]; aL[3] = zL32[ia1 + 4];
            #pragma unroll
            for (int nt = 0; nt < NT1; nt++) {
                int n = nh * 64 + nt * 8 + g;
                int ib = n * (PA1 / 2) + kt * 8 + q;
                unsigned bH[2] = {WaH32[ib], WaH32[ib + 4]};
                unsigned bL[2] = {WaL32[ib], WaL32[ib + 4]};
                mma_bf16(c1[nt], aH, bH);
                mma_bf16(c1[nt], aH, bL);
                mma_bf16(c1[nt], aL, bH);
            }
        }
        // epilogue 1: hidden = relu(c + ba), split into hHi/hLo
        #pragma unroll
        for (int nt = 0; nt < NT1; nt++) {
            int col0 = nh * 64 + nt * 8 + 2 * q;
            float b0 = ba_s[col0], b1 = ba_s[col0 + 1];
            float v0 = fmaxf(c1[nt][0] + b0, 0.f);
            float v1 = fmaxf(c1[nt][1] + b1, 0.f);
            float v2 = fmaxf(c1[nt][2] + b0, 0.f);
            float v3 = fmaxf(c1[nt][3] + b1, 0.f);
            unsigned h0, l0, h1, l1;
            split2(v0, v1, h0, l0);
            split2(v2, v3, h1, l1);
            int i0 = r0 * (PA2 / 2) + (col0 >> 1);
            int i1 = (r0 + 8) * (PA2 / 2) + (col0 >> 1);
            hH32[i0] = h0; hL32[i0] = l0;
            hH32[i1] = h1; hL32[i1] = l1;
        }
        __syncthreads();

        // ---- stage 2 ----
        float c2[NT2][4];
        #pragma unroll
        for (int nt = 0; nt < NT2; nt++)
            #pragma unroll
            for (int j = 0; j < 4; j++) c2[nt][j] = 0.f;
        #pragma unroll
        for (int kt = 0; kt < KT2; kt++) {
            unsigned aH[4], aL[4];
            int ia0 = r0 * (PA2 / 2) + kt * 8 + q;
            int ia1 = (r0 + 8) * (PA2 / 2) + kt * 8 + q;
            aH[0] = hH32[ia0]; aH[1] = hH32[ia1]; aH[2] = hH32[ia0 + 4]; aH[3] = hH32[ia1 + 4];
            aL[0] = hL32[ia0]; aL[1] = hL32[ia1]; aL[2] = hL32[ia0 + 4]; aL[3] = hL32[ia1 + 4];
            #pragma unroll
            for (int nt = 0; nt < NT2; nt++) {
                int n = nh * (D_OUT / 2) + nt * 8 + g;
                int ib = n * (PA2 / 2) + kt * 8 + q;
                unsigned bH[2] = {WbH32[ib], WbH32[ib + 4]};
                unsigned bL[2] = {WbL32[ib], WbL32[ib + 4]};
                mma_bf16(c2[nt], aH, bH);
                mma_bf16(c2[nt], aH, bL);
                mma_bf16(c2[nt], aL, bH);
            }
        }
        // epilogue 2: out = [relu](c + bb), float2 stores
        int node0 = tile0 + r0;
        int node1 = node0 + 8;
        #pragma unroll
        for (int nt = 0; nt < NT2; nt++) {
            int col0 = nh * (D_OUT / 2) + nt * 8 + 2 * q;
            float b0 = bb_s[col0], b1 = bb_s[col0 + 1];
            if (node0 < n_nodes) {
                float2 v = make_float2(c2[nt][0] + b0, c2[nt][1] + b1);
                if (RELU_OUT) { v.x = fmaxf(v.x, 0.f); v.y = fmaxf(v.y, 0.f); }
                *reinterpret_cast<float2*>(out + (size_t)node0 * D_OUT + col0) = v;
            }
            if (node1 < n_nodes) {
                float2 v = make_float2(c2[nt][2] + b0, c2[nt][3] + b1);
                if (RELU_OUT) { v.x = fmaxf(v.x, 0.f); v.y = fmaxf(v.y, 0.f); }
                *reinterpret_cast<float2*>(out + (size_t)node1 * D_OUT + col0) = v;
            }
        }
        __syncthreads();
    }
}

// ---------------------------------- launch -----------------------------------
extern "C" void kernel_launch(void* const* d_in, const int* in_sizes, int n_in,
                              void* d_out, int out_size) {
    const float* x    = (const float*)d_in[0];
    const int*   ei   = (const int*)d_in[1];
    const float* eps1 = (const float*)d_in[2];
    const float* eps2 = (const float*)d_in[3];
    const float* W1a  = (const float*)d_in[4];
    const float* b1a  = (const float*)d_in[5];
    const float* W1b  = (const float*)d_in[6];
    const float* b1b  = (const float*)d_in[7];
    const float* W2a  = (const float*)d_in[8];
    const float* b2a  = (const float*)d_in[9];
    const float* W2b  = (const float*)d_in[10];
    const float* b2b  = (const float*)d_in[11];
    float* out = (float*)d_out;

    const int n_nodes = in_sizes[0] / 64;
    const int n_edges = in_sizes[1] / 2;
    const int* src = ei;
    const int* dst = ei + n_edges;

    float *z1, *h, *z2;
    int *cnt, *off, *cur, *esrc, *bsum;
    cudaGetSymbolAddress((void**)&z1, g_z1);
    cudaGetSymbolAddress((void**)&h,  g_h);
    cudaGetSymbolAddress((void**)&z2, g_z2);
    cudaGetSymbolAddress((void**)&cnt, g_cnt);
    cudaGetSymbolAddress((void**)&off, g_off);
    cudaGetSymbolAddress((void**)&cur, g_cur);
    cudaGetSymbolAddress((void**)&esrc, g_esrc);
    cudaGetSymbolAddress((void**)&bsum, g_bsum);

    // smem sizes (match kernel constexpr layout)
    const int smem1 = 160768;   // L1: D_IN=64, D_OUT=128
    const int smem2 = 174848;   // L2: D_IN=128, D_OUT=64
    cudaFuncSetAttribute(mlp_mma_kernel<64, 128, true>,
                         cudaFuncAttributeMaxDynamicSharedMemorySize, smem1);
    cudaFuncSetAttribute(mlp_mma_kernel<128, 64, false>,
                         cudaFuncAttributeMaxDynamicSharedMemorySize, smem2);

    const int nscan = (n_nodes + SCAN_CHUNK - 1) / SCAN_CHUNK;
    const int ntiles = (n_nodes + 63) / 64;
    const int GRID = 148;

    // cnt is zero (zero-init at load / re-zeroed at end of previous call)
    hist_kernel<<<(n_edges + 255) / 256, 256>>>(dst, cnt, n_edges);                // 1
    scan_part_kernel<<<nscan, 256>>>(cnt, bsum, n_nodes);                          // 2
    scan_emit_kernel<<<nscan, 256>>>(cnt, bsum, off, cur, n_nodes, n_edges);       // 3
    fill_kernel<<<(n_edges + 255) / 256, 256>>>(src, dst, cur, esrc, n_edges);     // 4

    // layer 1
    {
        int nwarps = (n_nodes + 1) / 2;
        gather64_kernel<<<(nwarps * 32 + 255) / 256, 256>>>(x, off, esrc, eps1, z1, n_nodes); // 5
        mlp_mma_kernel<64, 128, true><<<GRID, 256, smem1>>>(
            z1, W1a, b1a, W1b, b1b, h, n_nodes, ntiles);                           // 6 (profiled)
    }
    // layer 2
    {
        gather128_kernel<<<(n_nodes * 32 + 255) / 256, 256>>>(h, off, esrc, eps2, z2, n_nodes); // 7
        mlp_mma_kernel<128, 64, false><<<GRID, 256, smem2>>>(
            z2, W2a, b2a, W2b, b2b, out, n_nodes, ntiles);                         // 8
    }

    // restore cnt = 0 for the next call (deterministic across replays)
    zero_kernel<<<(n_nodes + 255) / 256, 256>>>(cnt, n_nodes);                     // 9
}